// round 2
// baseline (speedup 1.0000x reference)
#include <cuda_runtime.h>
#include <math.h>
#include <stdint.h>

// Problem constants
#define NROW   4096
#define NT     512          // threads per block
#define RPT    8            // rows per thread (NROW / NT)
#define NCELL  5
#define MAXIT  150

// Shared layout (doubles):
//   r0[4096] r[4096] p[4097] s[4097] v[4096] t[4096] scr[46]
#define SM_DOUBLES (4096*2 + 4097*2 + 4096*2 + 46)

__device__ double g_IM[75];   // I_model scratch (3 systems x 25)

__device__ __forceinline__ double warp_red(double v) {
#pragma unroll
    for (int o = 16; o; o >>= 1) v += __shfl_down_sync(0xFFFFFFFFu, v, o);
    return v;
}

// Block reduction over 512 threads (16 warps). Two barriers.
// Safe for back-to-back reuse: the next call's first barrier orders the
// previous result-read before the next result-write.
__device__ __forceinline__ double blk_red(double v, double* scr, int tid) {
    int lane = tid & 31, wid = tid >> 5;
    v = warp_red(v);
    if (lane == 0) scr[wid] = v;
    __syncthreads();
    if (wid == 0) {
        double u = (lane < 16) ? scr[lane] : 0.0;
#pragma unroll
        for (int o = 8; o; o >>= 1) u += __shfl_down_sync(0xFFFFFFFFu, u, o);
        if (lane == 0) scr[32] = u;
    }
    __syncthreads();
    return scr[32];
}

__device__ __forceinline__ void blk_red2(double& a, double& b, double* scr, int tid) {
    int lane = tid & 31, wid = tid >> 5;
    a = warp_red(a);
    b = warp_red(b);
    if (lane == 0) { scr[wid] = a; scr[16 + wid] = b; }
    __syncthreads();
    if (wid == 0) {
        double ua = (lane < 16) ? scr[lane] : 0.0;
        double ub = (lane < 16) ? scr[16 + lane] : 0.0;
#pragma unroll
        for (int o = 8; o; o >>= 1) {
            ua += __shfl_down_sync(0xFFFFFFFFu, ua, o);
            ub += __shfl_down_sync(0xFFFFFFFFu, ub, o);
        }
        if (lane == 0) { scr[32] = ua; scr[33] = ub; }
    }
    __syncthreads();
    a = scr[32];
    b = scr[33];
}

__global__ __launch_bounds__(NT, 1)
void solve_kernel(const float* __restrict__ th1,
                  const float* __restrict__ th2,
                  const float* __restrict__ th3,
                  const float* __restrict__ cd,
                  const int*   __restrict__ nbr)
{
    extern __shared__ double sm[];
    double* r0  = sm;                // 4096
    double* rr  = sm + 4096;         // 4096
    double* pp  = sm + 8192;         // 4097 (pad slot 4096 == 0)
    double* ss  = pp + 4097;         // 4097 (pad slot 4096 == 0)
    double* vv  = ss + 4097;         // 4096
    double* tz  = vv + 4096;         // 4096
    double* scr = tz + 4096;         // 46

    const int tid = threadIdx.x;
    const int sys = blockIdx.x;
    const float* th = (sys == 0) ? th1 : ((sys == 1) ? th2 : th3);

    // Constants (match reference formulas; computed in double)
    const double L_C     = 8.45e-05;
    const double L_RATIO = 1.0 / sqrt(3.0);              // L_E / L_C
    const double AREA    = sqrt(3.0) * 0.5 * L_C * L_C;
    const double A_SCALE = 1.0e11;
    const double B_SCALE = 1.0e23;

    const double D   = (double)th[0];
    const double lam = (double)th[1];
    const double K   = (double)th[7];
    double rho[NCELL], rec[NCELL], recK[NCELL];
#pragma unroll
    for (int c = 0; c < NCELL; c++) {
        rho[c]  = (double)th[2 + c];
        rec[c]  = (double)th[8 + c];
        recK[c] = rec[c] * K;
    }
    const double Dp = D * L_RATIO;

    // Per-thread row state: packed neighbour indices (deduped, pad = 4096),
    // Jacobi weight w, solution x.
    uint32_t pk[RPT][3];
    double   w[RPT], x[RPT];

    double bb_part = 0.0;
#pragma unroll
    for (int t = 0; t < RPT; t++) {
        const int i = tid + t * NT;
        int nb[6];
#pragma unroll
        for (int j = 0; j < 6; j++) nb[j] = nbr[i * 6 + j];
        // Dedupe (set semantics): later duplicates point at pad slot 4096.
#pragma unroll
        for (int j = 1; j < 6; j++)
#pragma unroll
            for (int l = 0; l < 6; l++)
                if (l < j && nb[j] == nb[l]) nb[j] = NROW;
        pk[t][0] = (uint32_t)nb[0] | ((uint32_t)nb[1] << 16);
        pk[t][1] = (uint32_t)nb[2] | ((uint32_t)nb[3] << 16);
        pk[t][2] = (uint32_t)nb[4] | ((uint32_t)nb[5] << 16);

        double drec = 0.0, drho = 0.0;
#pragma unroll
        for (int c = 0; c < NCELL; c++) {
            double f = (double)cd[i * NCELL + c];
            drec += f * recK[c];
            drho += f * rho[c];
        }
        const double diag = 6.0 * Dp + AREA * (lam + drec);
        w[t] = Dp / diag;
        // Jacobi-preconditioned RHS of  (A*A_SCALE) g = b
        const double bh = AREA * drho * B_SCALE / (A_SCALE * diag);
        r0[i] = bh;
        rr[i] = bh;
        pp[i] = 0.0;
        vv[i] = 0.0;
        x[t]  = 0.0;
        bb_part += bh * bh;
    }
    if (tid == 0) { pp[NROW] = 0.0; ss[NROW] = 0.0; }
    __syncthreads();

    const double bb   = blk_red(bb_part, scr, tid);
    const double tol2 = bb * 1e-20;   // rel residual 1e-10

    double rho_o = 1.0, alpha = 1.0, omega = 1.0;

    for (int it = 0; it < MAXIT; it++) {
        // rho_n = <r0, r>, rnorm2 = <r, r>
        double a0 = 0.0, a1 = 0.0;
#pragma unroll
        for (int t = 0; t < RPT; t++) {
            const int i = tid + t * NT;
            const double ri = rr[i];
            a0 += r0[i] * ri;
            a1 += ri * ri;
        }
        blk_red2(a0, a1, scr, tid);
        if (a1 < tol2) break;
        const double rho_n = a0;
        if (fabs(rho_n) < 1e-290) break;
        const double beta = (rho_n / rho_o) * (alpha / omega);

        // p = r + beta * (p - omega * v)
#pragma unroll
        for (int t = 0; t < RPT; t++) {
            const int i = tid + t * NT;
            pp[i] = rr[i] + beta * (pp[i] - omega * vv[i]);
        }
        __syncthreads();

        // v = A_hat p  (A_hat = I - w * sum_{unique nb});  c0 = <r0, v>
        double c0 = 0.0;
#pragma unroll
        for (int t = 0; t < RPT; t++) {
            const int i = tid + t * NT;
            const uint32_t q0 = pk[t][0], q1 = pk[t][1], q2 = pk[t][2];
            double sum = pp[q0 & 0xFFFFu] + pp[q0 >> 16]
                       + pp[q1 & 0xFFFFu] + pp[q1 >> 16]
                       + pp[q2 & 0xFFFFu] + pp[q2 >> 16];
            const double vi = pp[i] - w[t] * sum;
            vv[i] = vi;
            c0 += r0[i] * vi;
        }
        c0 = blk_red(c0, scr, tid);
        if (fabs(c0) < 1e-290) break;
        alpha = rho_n / c0;

        // s = r - alpha * v
#pragma unroll
        for (int t = 0; t < RPT; t++) {
            const int i = tid + t * NT;
            ss[i] = rr[i] - alpha * vv[i];
        }
        __syncthreads();

        // t = A_hat s;  d0 = <t,s>, d1 = <t,t>
        double d0 = 0.0, d1 = 0.0;
#pragma unroll
        for (int t = 0; t < RPT; t++) {
            const int i = tid + t * NT;
            const uint32_t q0 = pk[t][0], q1 = pk[t][1], q2 = pk[t][2];
            double sum = ss[q0 & 0xFFFFu] + ss[q0 >> 16]
                       + ss[q1 & 0xFFFFu] + ss[q1 >> 16]
                       + ss[q2 & 0xFFFFu] + ss[q2 >> 16];
            const double ti = ss[i] - w[t] * sum;
            tz[i] = ti;
            d0 += ti * ss[i];
            d1 += ti * ti;
        }
        blk_red2(d0, d1, scr, tid);
        if (d1 == 0.0) {   // exact convergence at the s step
#pragma unroll
            for (int t = 0; t < RPT; t++) {
                const int i = tid + t * NT;
                x[t] += alpha * pp[i];
            }
            break;
        }
        omega = d0 / d1;

        // x += alpha p + omega s ;  r = s - omega t
#pragma unroll
        for (int t = 0; t < RPT; t++) {
            const int i = tid + t * NT;
            x[t]  += alpha * pp[i] + omega * ss[i];
            rr[i]  = ss[i] - omega * tz[i];
        }
        rho_o = rho_n;
    }

    // Epilogue: s_c = sum_i g_i * (cd[i,c]*rho_c / sum_c' cd[i,c']*rho_c')
    double part[NCELL] = {0, 0, 0, 0, 0};
#pragma unroll
    for (int t = 0; t < RPT; t++) {
        const int i = tid + t * NT;
        double num[NCELL], den = 0.0;
#pragma unroll
        for (int c = 0; c < NCELL; c++) {
            num[c] = (double)cd[i * NCELL + c] * rho[c];
            den += num[c];
        }
        const double gi = x[t] / den;
#pragma unroll
        for (int c = 0; c < NCELL; c++) part[c] += gi * num[c];
    }
    double sc[NCELL];
#pragma unroll
    for (int c = 0; c < NCELL; c++) sc[c] = blk_red(part[c], scr, tid);

    if (tid < 25) {
        const int a = tid / 5, c = tid % 5;
        g_IM[sys * 25 + tid] = K * rec[a] * sc[c] / (double)NROW;
    }
}

__global__ void loss_kernel(const float* __restrict__ Iexp, float* __restrict__ out)
{
    const int tid = threadIdx.x;   // 32 threads
    double s_m = 0, s_d = 0, s_mm = 0, s_dd = 0, s_md = 0;
    for (int i = tid; i < 75; i += 32) {
        const double m = g_IM[i];
        const double d = (double)Iexp[i];
        s_m += m; s_d += d; s_mm += m * m; s_dd += d * d; s_md += m * d;
    }
    s_m  = warp_red(s_m);
    s_d  = warp_red(s_d);
    s_mm = warp_red(s_mm);
    s_dd = warp_red(s_dd);
    s_md = warp_red(s_md);
    if (tid == 0) {
        const double n  = 75.0;
        const double mm = s_m / n, md = s_d / n;
        const double cov = s_md / n - mm * md;
        const double vm  = s_mm / n - mm * mm;
        const double vd  = s_dd / n - md * md;
        const double loss = 1.0 - cov / (sqrt(vm) * sqrt(vd));
        out[0] = (float)loss;
    }
}

extern "C" void kernel_launch(void* const* d_in, const int* in_sizes, int n_in,
                              void* d_out, int out_size)
{
    const float* th1  = (const float*)d_in[0];
    const float* th2  = (const float*)d_in[1];
    const float* th3  = (const float*)d_in[2];
    const float* cd   = (const float*)d_in[3];
    const float* Iexp = (const float*)d_in[4];
    const int*   nbr  = (const int*)d_in[5];

    const size_t smem = (size_t)SM_DOUBLES * sizeof(double);
    cudaFuncSetAttribute(solve_kernel,
                         cudaFuncAttributeMaxDynamicSharedMemorySize, (int)smem);

    solve_kernel<<<3, NT, smem>>>(th1, th2, th3, cd, nbr);
    loss_kernel<<<1, 32>>>(Iexp, (float*)d_out);
}

// round 3
// speedup vs baseline: 2.0885x; 2.0885x over previous
#include <cuda_runtime.h>
#include <math.h>
#include <stdint.h>

// Problem constants
#define NROW     4096
#define NT       512         // threads per block
#define RPT      8           // rows per thread
#define NCELL    5
#define MAXIT_IN 64          // max inner (fp32) BiCGStab iterations
#define MAX_OUTER 3          // max refinement passes

// Shared memory carve (bytes):
//   doubles: bhd[4096] xd[4096] scrd[40]            = 8232 * 8 = 65856
//   floats:  r0f rf pf(4097) sf(4097) vf tf scrf[38]= 24616 * 4 = 98464
#define SM_BYTES (8232*8 + 24616*4)

__device__ double g_IM[75];   // I_model scratch (3 systems x 25)

__device__ __forceinline__ float warp_red_f(float v) {
#pragma unroll
    for (int o = 16; o; o >>= 1) v += __shfl_down_sync(0xFFFFFFFFu, v, o);
    return v;
}
__device__ __forceinline__ double warp_red_d(double v) {
#pragma unroll
    for (int o = 16; o; o >>= 1) v += __shfl_down_sync(0xFFFFFFFFu, v, o);
    return v;
}

// Block reductions over 512 threads (16 warps), 2 barriers each.
__device__ __forceinline__ double blk_red_d(double v, double* scr, int tid) {
    int lane = tid & 31, wid = tid >> 5;
    v = warp_red_d(v);
    if (lane == 0) scr[wid] = v;
    __syncthreads();
    if (wid == 0) {
        double u = (lane < 16) ? scr[lane] : 0.0;
#pragma unroll
        for (int o = 8; o; o >>= 1) u += __shfl_down_sync(0xFFFFFFFFu, u, o);
        if (lane == 0) scr[32] = u;
    }
    __syncthreads();
    return scr[32];
}
__device__ __forceinline__ float blk_red_f(float v, float* scr, int tid) {
    int lane = tid & 31, wid = tid >> 5;
    v = warp_red_f(v);
    if (lane == 0) scr[wid] = v;
    __syncthreads();
    if (wid == 0) {
        float u = (lane < 16) ? scr[lane] : 0.0f;
#pragma unroll
        for (int o = 8; o; o >>= 1) u += __shfl_down_sync(0xFFFFFFFFu, u, o);
        if (lane == 0) scr[32] = u;
    }
    __syncthreads();
    return scr[32];
}
__device__ __forceinline__ void blk_red2_f(float& a, float& b, float* scr, int tid) {
    int lane = tid & 31, wid = tid >> 5;
    a = warp_red_f(a);
    b = warp_red_f(b);
    if (lane == 0) { scr[wid] = a; scr[16 + wid] = b; }
    __syncthreads();
    if (wid == 0) {
        float ua = (lane < 16) ? scr[lane] : 0.0f;
        float ub = (lane < 16) ? scr[16 + lane] : 0.0f;
#pragma unroll
        for (int o = 8; o; o >>= 1) {
            ua += __shfl_down_sync(0xFFFFFFFFu, ua, o);
            ub += __shfl_down_sync(0xFFFFFFFFu, ub, o);
        }
        if (lane == 0) { scr[32] = ua; scr[33] = ub; }
    }
    __syncthreads();
    a = scr[32];
    b = scr[33];
}

__global__ __launch_bounds__(NT, 1)
void solve_kernel(const float* __restrict__ th1,
                  const float* __restrict__ th2,
                  const float* __restrict__ th3,
                  const float* __restrict__ cd,
                  const int*   __restrict__ nbr)
{
    extern __shared__ double sm[];
    double* bhd  = sm;               // 4096 : RHS (Jacobi-preconditioned), fp64
    double* xd   = sm + 4096;        // 4096 : iterate staging for fp64 residual
    double* scrd = sm + 8192;        // 40
    float*  fb   = (float*)(sm + 8232);
    float* r0f = fb;                 // 4096
    float* rf  = fb + 4096;          // 4096
    float* pf  = fb + 8192;          // 4097 (pad slot 4096 == 0)
    float* sf  = fb + 12289;         // 4097 (pad slot 4096 == 0)
    float* vf  = fb + 16386;         // 4096
    float* tf  = fb + 20482;         // 4096
    float* scrf= fb + 24578;         // 38

    const int tid = threadIdx.x;
    const int sys = blockIdx.x;
    const float* th = (sys == 0) ? th1 : ((sys == 1) ? th2 : th3);

    // Constants (match reference, fp64)
    const double L_C     = 8.45e-05;
    const double L_RATIO = 1.0 / sqrt(3.0);
    const double AREA    = sqrt(3.0) * 0.5 * L_C * L_C;
    const double A_SCALE = 1.0e11;
    const double B_SCALE = 1.0e23;

    const double D   = (double)th[0];
    const double lam = (double)th[1];
    const double K   = (double)th[7];
    double rho[NCELL], rec[NCELL], recK[NCELL];
#pragma unroll
    for (int c = 0; c < NCELL; c++) {
        rho[c]  = (double)th[2 + c];
        rec[c]  = (double)th[8 + c];
        recK[c] = rec[c] * K;
    }
    const double Dp = D * L_RATIO;

    // Per-thread row state
    uint32_t pk[RPT][3];
    double   wd[RPT];       // Jacobi weight, fp64 (for refinement residual)
    float    wf[RPT];       // Jacobi weight, fp32 (hot loop)
    double   x[RPT];        // solution accumulator, fp64

    double bb_part = 0.0;
#pragma unroll
    for (int t = 0; t < RPT; t++) {
        const int i = tid + t * NT;
        int nb[6];
#pragma unroll
        for (int j = 0; j < 6; j++) nb[j] = nbr[i * 6 + j];
        // Dedupe (set semantics): duplicates -> pad slot 4096 (which holds 0)
#pragma unroll
        for (int j = 1; j < 6; j++)
#pragma unroll
            for (int l = 0; l < 6; l++)
                if (l < j && nb[j] == nb[l]) nb[j] = NROW;
        pk[t][0] = (uint32_t)nb[0] | ((uint32_t)nb[1] << 16);
        pk[t][1] = (uint32_t)nb[2] | ((uint32_t)nb[3] << 16);
        pk[t][2] = (uint32_t)nb[4] | ((uint32_t)nb[5] << 16);

        double drec = 0.0, drho = 0.0;
#pragma unroll
        for (int c = 0; c < NCELL; c++) {
            double f = (double)cd[i * NCELL + c];
            drec += f * recK[c];
            drho += f * rho[c];
        }
        const double diag = 6.0 * Dp + AREA * (lam + drec);
        wd[t] = Dp / diag;
        wf[t] = (float)wd[t];
        const double bh = AREA * drho * B_SCALE / (A_SCALE * diag);
        bhd[i]  = bh;
        r0f[i]  = (float)bh;
        rf[i]   = (float)bh;
        pf[i]   = 0.0f;
        vf[i]   = 0.0f;
        x[t]    = 0.0;
        bb_part += bh * bh;
    }
    if (tid == 0) { pf[NROW] = 0.0f; sf[NROW] = 0.0f; }
    __syncthreads();

    const double bb = blk_red_d(bb_part, scrd, tid);
    double rn2 = bb;   // squared norm of current outer residual

    for (int outer = 0; outer < MAX_OUTER; outer++) {
        if (outer > 0 && rn2 <= bb * 1e-16) break;   // relres 1e-8 reached

        // ---- fp32 BiCGStab on  A_hat d = r  (d accumulated into fp64 x) ----
        const float tol2 = (float)(rn2 * 1e-10);     // inner relres 1e-5
        float rho_o = 1.0f, alpha = 1.0f, omega = 1.0f;

        for (int it = 0; it < MAXIT_IN; it++) {
            float a0 = 0.0f, a1 = 0.0f;
#pragma unroll
            for (int t = 0; t < RPT; t++) {
                const int i = tid + t * NT;
                const float ri = rf[i];
                a0 += r0f[i] * ri;
                a1 += ri * ri;
            }
            blk_red2_f(a0, a1, scrf, tid);
            if (a1 <= tol2 || a1 < 1e-32f) break;
            if (fabsf(a0) < 1e-35f) break;           // breakdown -> refinement restarts
            const float beta = (a0 / rho_o) * (alpha / omega);

            // p = r + beta * (p - omega * v)
#pragma unroll
            for (int t = 0; t < RPT; t++) {
                const int i = tid + t * NT;
                pf[i] = rf[i] + beta * (pf[i] - omega * vf[i]);
            }
            __syncthreads();

            // v = A_hat p ; c0 = <r0, v>
            float c0 = 0.0f;
#pragma unroll
            for (int t = 0; t < RPT; t++) {
                const int i = tid + t * NT;
                const uint32_t q0 = pk[t][0], q1 = pk[t][1], q2 = pk[t][2];
                float sum = pf[q0 & 0xFFFFu] + pf[q0 >> 16]
                          + pf[q1 & 0xFFFFu] + pf[q1 >> 16]
                          + pf[q2 & 0xFFFFu] + pf[q2 >> 16];
                const float vi = pf[i] - wf[t] * sum;
                vf[i] = vi;
                c0 += r0f[i] * vi;
            }
            c0 = blk_red_f(c0, scrf, tid);
            if (fabsf(c0) < 1e-35f) break;
            alpha = a0 / c0;

            // s = r - alpha * v
#pragma unroll
            for (int t = 0; t < RPT; t++) {
                const int i = tid + t * NT;
                sf[i] = rf[i] - alpha * vf[i];
            }
            __syncthreads();

            // t = A_hat s ; d0 = <t,s>, d1 = <t,t>
            float d0 = 0.0f, d1 = 0.0f;
#pragma unroll
            for (int t = 0; t < RPT; t++) {
                const int i = tid + t * NT;
                const uint32_t q0 = pk[t][0], q1 = pk[t][1], q2 = pk[t][2];
                float sum = sf[q0 & 0xFFFFu] + sf[q0 >> 16]
                          + sf[q1 & 0xFFFFu] + sf[q1 >> 16]
                          + sf[q2 & 0xFFFFu] + sf[q2 >> 16];
                const float ti = sf[i] - wf[t] * sum;
                tf[i] = ti;
                d0 += ti * sf[i];
                d1 += ti * ti;
            }
            blk_red2_f(d0, d1, scrf, tid);
            if (d1 <= 0.0f) {
#pragma unroll
                for (int t = 0; t < RPT; t++) {
                    const int i = tid + t * NT;
                    x[t] += (double)alpha * (double)pf[i];
                }
                break;
            }
            omega = d0 / d1;

            // x += alpha p + omega s ; r = s - omega t
#pragma unroll
            for (int t = 0; t < RPT; t++) {
                const int i = tid + t * NT;
                x[t] += (double)alpha * (double)pf[i] + (double)omega * (double)sf[i];
                rf[i] = sf[i] - omega * tf[i];
            }
            rho_o = a0;
        }

        // ---- fp64 residual: r = bh - A_hat x ; stage as next fp32 RHS ----
#pragma unroll
        for (int t = 0; t < RPT; t++) xd[tid + t * NT] = x[t];
        __syncthreads();
        double rp = 0.0;
#pragma unroll
        for (int t = 0; t < RPT; t++) {
            const int i = tid + t * NT;
            const uint32_t q0 = pk[t][0], q1 = pk[t][1], q2 = pk[t][2];
            // pad slot: xd has no pad, so mask to 4095 and zero-select
            const int i0 = q0 & 0xFFFFu, i1 = q0 >> 16;
            const int i2 = q1 & 0xFFFFu, i3 = q1 >> 16;
            const int i4 = q2 & 0xFFFFu, i5 = q2 >> 16;
            double sum = 0.0;
            sum += (i0 < NROW) ? xd[i0] : 0.0;
            sum += (i1 < NROW) ? xd[i1] : 0.0;
            sum += (i2 < NROW) ? xd[i2] : 0.0;
            sum += (i3 < NROW) ? xd[i3] : 0.0;
            sum += (i4 < NROW) ? xd[i4] : 0.0;
            sum += (i5 < NROW) ? xd[i5] : 0.0;
            const double rdi = bhd[i] - (xd[i] - wd[t] * sum);
            const float  rdf = (float)rdi;
            r0f[i] = rdf;
            rf[i]  = rdf;
            pf[i]  = 0.0f;
            vf[i]  = 0.0f;
            rp += rdi * rdi;
        }
        rn2 = blk_red_d(rp, scrd, tid);   // also the barrier before next phase
    }

    // ---- Epilogue (fp64) ----
    double part[NCELL] = {0, 0, 0, 0, 0};
#pragma unroll
    for (int t = 0; t < RPT; t++) {
        const int i = tid + t * NT;
        double num[NCELL], den = 0.0;
#pragma unroll
        for (int c = 0; c < NCELL; c++) {
            num[c] = (double)cd[i * NCELL + c] * rho[c];
            den += num[c];
        }
        const double gi = x[t] / den;
#pragma unroll
        for (int c = 0; c < NCELL; c++) part[c] += gi * num[c];
    }
    double sc[NCELL];
#pragma unroll
    for (int c = 0; c < NCELL; c++) sc[c] = blk_red_d(part[c], scrd, tid);

    if (tid < 25) {
        const int a = tid / 5, c = tid % 5;
        g_IM[sys * 25 + tid] = K * rec[a] * sc[c] / (double)NROW;
    }
}

__global__ void loss_kernel(const float* __restrict__ Iexp, float* __restrict__ out)
{
    const int tid = threadIdx.x;   // 32 threads
    double s_m = 0, s_d = 0, s_mm = 0, s_dd = 0, s_md = 0;
    for (int i = tid; i < 75; i += 32) {
        const double m = g_IM[i];
        const double d = (double)Iexp[i];
        s_m += m; s_d += d; s_mm += m * m; s_dd += d * d; s_md += m * d;
    }
    s_m  = warp_red_d(s_m);
    s_d  = warp_red_d(s_d);
    s_mm = warp_red_d(s_mm);
    s_dd = warp_red_d(s_dd);
    s_md = warp_red_d(s_md);
    if (tid == 0) {
        const double n  = 75.0;
        const double mm = s_m / n, md = s_d / n;
        const double cov = s_md / n - mm * md;
        const double vm  = s_mm / n - mm * mm;
        const double vd  = s_dd / n - md * md;
        out[0] = (float)(1.0 - cov / (sqrt(vm) * sqrt(vd)));
    }
}

extern "C" void kernel_launch(void* const* d_in, const int* in_sizes, int n_in,
                              void* d_out, int out_size)
{
    const float* th1  = (const float*)d_in[0];
    const float* th2  = (const float*)d_in[1];
    const float* th3  = (const float*)d_in[2];
    const float* cd   = (const float*)d_in[3];
    const float* Iexp = (const float*)d_in[4];
    const int*   nbr  = (const int*)d_in[5];

    cudaFuncSetAttribute(solve_kernel,
                         cudaFuncAttributeMaxDynamicSharedMemorySize, SM_BYTES);

    solve_kernel<<<3, NT, SM_BYTES>>>(th1, th2, th3, cd, nbr);
    loss_kernel<<<1, 32>>>(Iexp, (float*)d_out);
}

// round 4
// speedup vs baseline: 2.3492x; 1.1248x over previous
#include <cuda_runtime.h>
#include <math.h>
#include <stdint.h>

#define NROW      4096
#define NT        512        // threads per block
#define RPT       8          // rows per thread
#define NCELL     5
#define MAXIT_IN  48         // max inner (fp32) BiCGStab iterations per pass
#define MAX_OUTER 4          // max refinement passes

// smem: doubles xd[4097] scrd[47]  then floats pf[4097] sf[4097] r0f[4096] scrf[96]
#define SM_BYTES ((4097+47)*8 + (4097+4097+4096+96)*4)

__device__ double g_IM[75];    // I_model (3 systems x 25)
__device__ int    g_cnt = 0;   // last-block-done counter

__device__ __forceinline__ float warp_red_f(float v) {
#pragma unroll
    for (int o = 16; o; o >>= 1) v += __shfl_down_sync(0xFFFFFFFFu, v, o);
    return v;
}
__device__ __forceinline__ double warp_red_d(double v) {
#pragma unroll
    for (int o = 16; o; o >>= 1) v += __shfl_down_sync(0xFFFFFFFFu, v, o);
    return v;
}

__device__ __forceinline__ double blk_red_d(double v, double* scr, int tid) {
    int lane = tid & 31, wid = tid >> 5;
    v = warp_red_d(v);
    if (lane == 0) scr[wid] = v;
    __syncthreads();
    if (wid == 0) {
        double u = (lane < 16) ? scr[lane] : 0.0;
#pragma unroll
        for (int o = 8; o; o >>= 1) u += __shfl_down_sync(0xFFFFFFFFu, u, o);
        if (lane == 0) scr[32] = u;
    }
    __syncthreads();
    return scr[32];
}
__device__ __forceinline__ float blk_red_f(float v, float* scr, int tid) {
    int lane = tid & 31, wid = tid >> 5;
    v = warp_red_f(v);
    if (lane == 0) scr[wid] = v;
    __syncthreads();
    if (wid == 0) {
        float u = (lane < 16) ? scr[lane] : 0.0f;
#pragma unroll
        for (int o = 8; o; o >>= 1) u += __shfl_down_sync(0xFFFFFFFFu, u, o);
        if (lane == 0) scr[32] = u;
    }
    __syncthreads();
    return scr[32];
}
// 5-way fused block reduction (one barrier pair for all five)
__device__ __forceinline__ void blk_red5_f(float v[5], float* scr, int tid) {
    int lane = tid & 31, wid = tid >> 5;
#pragma unroll
    for (int k = 0; k < 5; k++) v[k] = warp_red_f(v[k]);
    if (lane == 0) {
#pragma unroll
        for (int k = 0; k < 5; k++) scr[k * 16 + wid] = v[k];
    }
    __syncthreads();
    if (wid == 0) {
        float u[5];
#pragma unroll
        for (int k = 0; k < 5; k++) u[k] = (lane < 16) ? scr[k * 16 + lane] : 0.0f;
#pragma unroll
        for (int o = 8; o; o >>= 1)
#pragma unroll
            for (int k = 0; k < 5; k++) u[k] += __shfl_down_sync(0xFFFFFFFFu, u[k], o);
        if (lane == 0) {
#pragma unroll
            for (int k = 0; k < 5; k++) scr[80 + k] = u[k];
        }
    }
    __syncthreads();
#pragma unroll
    for (int k = 0; k < 5; k++) v[k] = scr[80 + k];
}

__global__ __launch_bounds__(NT, 1)
void solve_kernel(const float* __restrict__ th1,
                  const float* __restrict__ th2,
                  const float* __restrict__ th3,
                  const float* __restrict__ cd,
                  const float* __restrict__ Iexp,
                  const int*   __restrict__ nbr,
                  float*       __restrict__ out)
{
    extern __shared__ double sm[];
    double* xd   = sm;               // 4097 (pad slot 4096 == 0)
    double* scrd = sm + 4097;        // 47
    float*  fb   = (float*)(sm + 4144);
    float* pf   = fb;                // 4097 (pad slot 4096 == 0)
    float* sf   = fb + 4097;         // 4097 (pad slot 4096 == 0)
    float* r0f  = fb + 8194;         // 4096
    float* scrf = fb + 12290;        // 96
    __shared__ int s_last;

    const int tid = threadIdx.x;
    const int sys = blockIdx.x;
    const float* th = (sys == 0) ? th1 : ((sys == 1) ? th2 : th3);

    // fp64 constants (match reference)
    const double L_C     = 8.45e-05;
    const double L_RATIO = 1.0 / sqrt(3.0);
    const double AREA    = sqrt(3.0) * 0.5 * L_C * L_C;
    const double A_SCALE = 1.0e11;
    const double B_SCALE = 1.0e23;

    const double D   = (double)th[0];
    const double lam = (double)th[1];
    const double K   = (double)th[7];
    double rho[NCELL], rec[NCELL], recK[NCELL];
#pragma unroll
    for (int c = 0; c < NCELL; c++) {
        rho[c]  = (double)th[2 + c];
        rec[c]  = (double)th[8 + c];
        recK[c] = rec[c] * K;
    }
    const double Dp = D * L_RATIO;

    // Per-thread state (registers)
    uint32_t pk[RPT][3];
    float    wf[RPT];
    float    rg[RPT], pg[RPT], vg[RPT], sg[RPT], tg[RPT];
    double   x[RPT];

    // ---- setup: dedupe neighbours, diag, RHS ----
    double bb_part = 0.0;
#pragma unroll
    for (int t = 0; t < RPT; t++) {
        const int i = tid + t * NT;
        int nb[6];
#pragma unroll
        for (int j = 0; j < 6; j++) nb[j] = nbr[i * 6 + j];
#pragma unroll
        for (int j = 1; j < 6; j++)
#pragma unroll
            for (int l = 0; l < 6; l++)
                if (l < j && nb[j] == nb[l]) nb[j] = NROW;   // duplicate -> pad slot
        pk[t][0] = (uint32_t)nb[0] | ((uint32_t)nb[1] << 16);
        pk[t][1] = (uint32_t)nb[2] | ((uint32_t)nb[3] << 16);
        pk[t][2] = (uint32_t)nb[4] | ((uint32_t)nb[5] << 16);

        double drec = 0.0, drho = 0.0;
#pragma unroll
        for (int c = 0; c < NCELL; c++) {
            double f = (double)cd[i * NCELL + c];
            drec += f * recK[c];
            drho += f * rho[c];
        }
        const double diag = 6.0 * Dp + AREA * (lam + drec);
        wf[t] = (float)(Dp / diag);
        const double bh = AREA * drho * B_SCALE / (A_SCALE * diag);
        const float bhf = (float)bh;
        r0f[i] = bhf;
        rg[t]  = bhf;
        pg[t]  = 0.0f;
        vg[t]  = 0.0f;
        x[t]   = 0.0;
        bb_part += bh * bh;
    }
    if (tid == 0) { pf[NROW] = 0.0f; sf[NROW] = 0.0f; xd[NROW] = 0.0; }
    __syncthreads();

    const double bb   = blk_red_d(bb_part, scrd, tid);
    const double tolo = bb * 9e-16;        // outer: relres 3e-8
    double rn2d = bb;                      // true residual^2 entering this pass

    for (int outer = 0; outer < MAX_OUTER; outer++) {
        if (rn2d <= tolo) break;

        // inner target: relres 5e-4 of pass entry, floored at outer target
        float tol2 = (float)fmax(rn2d * 2.5e-7, tolo);
        float rho_n = (float)rn2d, rn2 = (float)rn2d;
        float rho_o = 1.0f, alpha = 1.0f, omega = 1.0f;
        float best = rn2; int since = 0;

        for (int it = 0; it < MAXIT_IN; it++) {
            const float beta = (rho_n / rho_o) * (alpha / omega);

            // p = r + beta*(p - omega*v)  -> publish
#pragma unroll
            for (int t = 0; t < RPT; t++) {
                pg[t] = rg[t] + beta * (pg[t] - omega * vg[t]);
                pf[tid + t * NT] = pg[t];
            }
            __syncthreads();

            // v = A_hat p ; c0 = <r0,v>
            float c0 = 0.0f;
#pragma unroll
            for (int t = 0; t < RPT; t++) {
                const int i = tid + t * NT;
                const uint32_t q0 = pk[t][0], q1 = pk[t][1], q2 = pk[t][2];
                float sum = pf[q0 & 0xFFFFu] + pf[q0 >> 16]
                          + pf[q1 & 0xFFFFu] + pf[q1 >> 16]
                          + pf[q2 & 0xFFFFu] + pf[q2 >> 16];
                vg[t] = pg[t] - wf[t] * sum;
                c0 += r0f[i] * vg[t];
            }
            c0 = blk_red_f(c0, scrf, tid);
            if (fabsf(c0) < 1e-35f) break;
            alpha = rho_n / c0;

            // s = r - alpha*v -> publish
#pragma unroll
            for (int t = 0; t < RPT; t++) {
                sg[t] = rg[t] - alpha * vg[t];
                sf[tid + t * NT] = sg[t];
            }
            __syncthreads();

            // t = A_hat s ; fused 5 dots: [st, tt, sr0, tr0, ss]
            float dt[5] = {0.0f, 0.0f, 0.0f, 0.0f, 0.0f};
#pragma unroll
            for (int t = 0; t < RPT; t++) {
                const int i = tid + t * NT;
                const uint32_t q0 = pk[t][0], q1 = pk[t][1], q2 = pk[t][2];
                float sum = sf[q0 & 0xFFFFu] + sf[q0 >> 16]
                          + sf[q1 & 0xFFFFu] + sf[q1 >> 16]
                          + sf[q2 & 0xFFFFu] + sf[q2 >> 16];
                tg[t] = sg[t] - wf[t] * sum;
                const float r0i = r0f[i];
                dt[0] += tg[t] * sg[t];
                dt[1] += tg[t] * tg[t];
                dt[2] += sg[t] * r0i;
                dt[3] += tg[t] * r0i;
                dt[4] += sg[t] * sg[t];
            }
            blk_red5_f(dt, scrf, tid);
            if (!(dt[1] > 0.0f)) {
#pragma unroll
                for (int t = 0; t < RPT; t++) x[t] += (double)alpha * (double)pg[t];
                break;
            }
            omega = dt[0] / dt[1];

            // x += alpha p + omega s ; r = s - omega t
#pragma unroll
            for (int t = 0; t < RPT; t++) {
                x[t] += (double)alpha * (double)pg[t] + (double)omega * (double)sg[t];
                rg[t] = sg[t] - omega * tg[t];
            }
            rho_o = rho_n;
            rho_n = dt[2] - omega * dt[3];                       // <r0, r_new>
            rn2   = fabsf(dt[4] - omega * (2.0f * dt[0] - omega * dt[1])); // |r_new|^2
            if (rn2 <= tol2) break;
            if (rn2 < best) { best = rn2; since = 0; }
            else if (++since >= 8) break;                        // stagnation
            if (fabsf(rho_n) < 1e-35f) break;
        }

        // ---- fp64 true residual: r = bh - A_hat x ; restart fp32 state ----
#pragma unroll
        for (int t = 0; t < RPT; t++) xd[tid + t * NT] = x[t];
        __syncthreads();
        double rp = 0.0;
#pragma unroll
        for (int t = 0; t < RPT; t++) {
            const int i = tid + t * NT;
            const uint32_t q0 = pk[t][0], q1 = pk[t][1], q2 = pk[t][2];
            double sum = xd[q0 & 0xFFFFu] + xd[q0 >> 16]
                       + xd[q1 & 0xFFFFu] + xd[q1 >> 16]
                       + xd[q2 & 0xFFFFu] + xd[q2 >> 16];
            double drec = 0.0, drho = 0.0;
#pragma unroll
            for (int c = 0; c < NCELL; c++) {
                double f = (double)cd[i * NCELL + c];
                drec += f * recK[c];
                drho += f * rho[c];
            }
            const double diag = 6.0 * Dp + AREA * (lam + drec);
            const double wdv  = Dp / diag;
            const double bh   = AREA * drho * B_SCALE / (A_SCALE * diag);
            const double rdi  = bh - (xd[i] - wdv * sum);
            const float  rdf  = (float)rdi;
            r0f[i] = rdf;
            rg[t]  = rdf;
            pg[t]  = 0.0f;
            vg[t]  = 0.0f;
            rp += rdi * rdi;
        }
        rn2d = blk_red_d(rp, scrd, tid);   // barrier also orders r0f writes
    }

    // ---- epilogue: s_c = sum_i g_i * cd[i,c]*rho_c / den_i ----
    double part[NCELL] = {0, 0, 0, 0, 0};
#pragma unroll
    for (int t = 0; t < RPT; t++) {
        const int i = tid + t * NT;
        double num[NCELL], den = 0.0;
#pragma unroll
        for (int c = 0; c < NCELL; c++) {
            num[c] = (double)cd[i * NCELL + c] * rho[c];
            den += num[c];
        }
        const double gi = x[t] / den;
#pragma unroll
        for (int c = 0; c < NCELL; c++) part[c] += gi * num[c];
    }
    double sc[NCELL];
#pragma unroll
    for (int c = 0; c < NCELL; c++) sc[c] = blk_red_d(part[c], scrd, tid);

    if (tid < 25) {
        const int a = tid / 5, c = tid % 5;
        g_IM[sys * 25 + tid] = K * rec[a] * sc[c] / (double)NROW;
    }

    // ---- last block computes the loss (fused; saves a launch) ----
    if (tid == 0) {
        __threadfence();
        s_last = (atomicAdd(&g_cnt, 1) == 2) ? 1 : 0;
    }
    __syncthreads();
    if (s_last && tid < 32) {
        __threadfence();
        double s_m = 0, s_d = 0, s_mm = 0, s_dd = 0, s_md = 0;
        for (int i = tid; i < 75; i += 32) {
            const double m = *((volatile double*)&g_IM[i]);
            const double d = (double)Iexp[i];
            s_m += m; s_d += d; s_mm += m * m; s_dd += d * d; s_md += m * d;
        }
        s_m  = warp_red_d(s_m);
        s_d  = warp_red_d(s_d);
        s_mm = warp_red_d(s_mm);
        s_dd = warp_red_d(s_dd);
        s_md = warp_red_d(s_md);
        if (tid == 0) {
            const double n  = 75.0;
            const double mm = s_m / n, md = s_d / n;
            const double cov = s_md / n - mm * md;
            const double vm  = s_mm / n - mm * mm;
            const double vd  = s_dd / n - md * md;
            out[0] = (float)(1.0 - cov / (sqrt(vm) * sqrt(vd)));
            atomicExch(&g_cnt, 0);   // reset for next graph replay
        }
    }
}

extern "C" void kernel_launch(void* const* d_in, const int* in_sizes, int n_in,
                              void* d_out, int out_size)
{
    const float* th1  = (const float*)d_in[0];
    const float* th2  = (const float*)d_in[1];
    const float* th3  = (const float*)d_in[2];
    const float* cd   = (const float*)d_in[3];
    const float* Iexp = (const float*)d_in[4];
    const int*   nbr  = (const int*)d_in[5];

    cudaFuncSetAttribute(solve_kernel,
                         cudaFuncAttributeMaxDynamicSharedMemorySize, SM_BYTES);

    solve_kernel<<<3, NT, SM_BYTES>>>(th1, th2, th3, cd, Iexp, nbr, (float*)d_out);
}

// round 5
// speedup vs baseline: 3.8592x; 1.6428x over previous
#include <cuda_runtime.h>
#include <math.h>
#include <stdint.h>

#define NROW      4096
#define NT        512
#define RPT       8
#define NCELL     5
#define MAXIT_IN  40
#define MAX_OUTER 4

// smem: xd[4097] dbl, scrd[40] dbl, pf[4097] f, sf[4097] f, scrf[96] f
#define SM_BYTES ((4097 + 40) * 8 + (4097 + 4097 + 96) * 4)

__device__ double g_IM[75];    // I_model (3 systems x 25)
__device__ int    g_cnt = 0;   // last-block-done counter

__device__ __forceinline__ double warp_red_d(double v) {
#pragma unroll
    for (int o = 16; o; o >>= 1) v += __shfl_down_sync(0xFFFFFFFFu, v, o);
    return v;
}
__device__ __forceinline__ double blk_red_d(double v, double* scr, int tid) {
    int lane = tid & 31, wid = tid >> 5;
    v = warp_red_d(v);
    if (lane == 0) scr[wid] = v;
    __syncthreads();
    if (wid == 0) {
        double u = (lane < 16) ? scr[lane] : 0.0;
#pragma unroll
        for (int o = 8; o; o >>= 1) u += __shfl_down_sync(0xFFFFFFFFu, u, o);
        if (lane == 0) scr[32] = u;
    }
    __syncthreads();
    return scr[32];
}

// Single-barrier block reductions (16 warps): warp shfl_xor pre-reduce,
// lane0 STS, one BAR, every thread reads scr[lane&15] + 4-level bfly.
// Caller must pass a scr region not concurrently reused (see call sites).
__device__ __forceinline__ float bred1(float v, float* scr, int tid) {
    const int lane = tid & 31, wid = tid >> 5;
#pragma unroll
    for (int o = 16; o; o >>= 1) v += __shfl_xor_sync(0xFFFFFFFFu, v, o);
    if (lane == 0) scr[wid] = v;
    __syncthreads();
    float u = scr[lane & 15];
#pragma unroll
    for (int o = 8; o; o >>= 1) u += __shfl_xor_sync(0xFFFFFFFFu, u, o);
    return u;
}
__device__ __forceinline__ void bred2(float& a, float& b, float* scr, int tid) {
    const int lane = tid & 31, wid = tid >> 5;
#pragma unroll
    for (int o = 16; o; o >>= 1) {
        a += __shfl_xor_sync(0xFFFFFFFFu, a, o);
        b += __shfl_xor_sync(0xFFFFFFFFu, b, o);
    }
    if (lane == 0) { scr[wid] = a; scr[16 + wid] = b; }
    __syncthreads();
    float ua = scr[lane & 15];
    float ub = scr[16 + (lane & 15)];
#pragma unroll
    for (int o = 8; o; o >>= 1) {
        ua += __shfl_xor_sync(0xFFFFFFFFu, ua, o);
        ub += __shfl_xor_sync(0xFFFFFFFFu, ub, o);
    }
    a = ua; b = ub;
}

__global__ __launch_bounds__(NT, 1)
void solve_kernel(const float* __restrict__ th1,
                  const float* __restrict__ th2,
                  const float* __restrict__ th3,
                  const float* __restrict__ cd,
                  const float* __restrict__ Iexp,
                  const int*   __restrict__ nbr,
                  float*       __restrict__ out)
{
    extern __shared__ double sm[];
    double* xd   = sm;               // 4097 doubles (pad slot 4096 == 0)
    double* scrd = sm + 4097;        // 40
    float*  fb   = (float*)(sm + 4137);
    float* pf   = fb;                // 4097 (pad slot 4096 == 0)
    float* sf   = fb + 4097;         // 4097 (pad slot 4096 == 0)
    float* scrf = fb + 8194;         // 96 : [0..15] red1, [16..47] red2, [48..79] red3
    __shared__ int s_last;

    const int tid = threadIdx.x;
    const int sys = blockIdx.x;
    const float* th = (sys == 0) ? th1 : ((sys == 1) ? th2 : th3);

    // fp64 constants (match reference)
    const double L_C     = 8.45e-05;
    const double L_RATIO = 1.0 / sqrt(3.0);
    const double AREA    = sqrt(3.0) * 0.5 * L_C * L_C;
    const double A_SCALE = 1.0e11;
    const double B_SCALE = 1.0e23;

    const double D   = (double)th[0];
    const double lam = (double)th[1];
    const double K   = (double)th[7];
    double rho_p[NCELL], rec[NCELL], recK[NCELL];
#pragma unroll
    for (int c = 0; c < NCELL; c++) {
        rho_p[c] = (double)th[2 + c];
        rec[c]   = (double)th[8 + c];
        recK[c]  = rec[c] * K;
    }
    const double Dp = D * L_RATIO;

    // Per-thread register state (all fp32 in hot loop)
    uint32_t pk[RPT][3];                 // packed byte offsets (idx*4), pad = 4096*4
    float wf[RPT], r0g[RPT];
    float rg[RPT], pg[RPT], vg[RPT], sg[RPT], tg[RPT], dx[RPT];

    // ---- setup ----
    double bb_part = 0.0;
#pragma unroll
    for (int t = 0; t < RPT; t++) {
        const int i = tid + t * NT;
        int nb[6];
#pragma unroll
        for (int j = 0; j < 6; j++) nb[j] = nbr[i * 6 + j];
#pragma unroll
        for (int j = 1; j < 6; j++)
#pragma unroll
            for (int l = 0; l < 6; l++)
                if (l < j && nb[j] == nb[l]) nb[j] = NROW;   // dup -> pad slot
        pk[t][0] = ((uint32_t)nb[0] * 4u) | (((uint32_t)nb[1] * 4u) << 16);
        pk[t][1] = ((uint32_t)nb[2] * 4u) | (((uint32_t)nb[3] * 4u) << 16);
        pk[t][2] = ((uint32_t)nb[4] * 4u) | (((uint32_t)nb[5] * 4u) << 16);

        double drec = 0.0, drho = 0.0;
#pragma unroll
        for (int c = 0; c < NCELL; c++) {
            double f = (double)cd[i * NCELL + c];
            drec += f * recK[c];
            drho += f * rho_p[c];
        }
        const double diag = 6.0 * Dp + AREA * (lam + drec);
        wf[t] = (float)(Dp / diag);
        const double bh = AREA * drho * B_SCALE / (A_SCALE * diag);
        const float bhf = (float)bh;
        r0g[t] = bhf; rg[t] = bhf;
        pg[t] = 0.0f; vg[t] = 0.0f; dx[t] = 0.0f;
        xd[i] = 0.0;
        bb_part += bh * bh;
    }
    if (tid == 0) { pf[NROW] = 0.0f; sf[NROW] = 0.0f; xd[NROW] = 0.0; }
    __syncthreads();

    const double bb   = blk_red_d(bb_part, scrd, tid);
    const double tolo = bb * 9e-16;      // outer relres 3e-8
    double rn2d = bb;

#define GATH(arr, q0, q1, q2)                                                 \
    ( *(const float*)((const char*)(arr) + ((q0) & 0xFFFFu))                  \
    + *(const float*)((const char*)(arr) + ((q0) >> 16))                      \
    + *(const float*)((const char*)(arr) + ((q1) & 0xFFFFu))                  \
    + *(const float*)((const char*)(arr) + ((q1) >> 16))                      \
    + *(const float*)((const char*)(arr) + ((q2) & 0xFFFFu))                  \
    + *(const float*)((const char*)(arr) + ((q2) >> 16)) )

    for (int outer = 0; outer < MAX_OUTER && rn2d > tolo; outer++) {
        const float tol2 = (float)fmax(rn2d * 1e-8, tolo);   // inner relres 1e-4
        float rho = (float)rn2d, rn2 = rho;
        float rho_o = 1.0f, alpha = 1.0f, omega = 1.0f;
        float best = rn2; int since = 0;

        for (int it = 0; it < MAXIT_IN; it++) {
            const float beta = (it == 0) ? 0.0f
                             : __fdividef(rho * alpha, rho_o * omega);

            // p = r + beta*(p - omega*v) ; publish
#pragma unroll
            for (int t = 0; t < RPT; t++) {
                pg[t] = fmaf(beta, fmaf(-omega, vg[t], pg[t]), rg[t]);
                pf[tid + t * NT] = pg[t];
            }
            __syncthreads();

            // v = A_hat p ; c0 = <r0,v>
            float c0 = 0.0f;
#pragma unroll
            for (int t = 0; t < RPT; t++) {
                const float sum = GATH(pf, pk[t][0], pk[t][1], pk[t][2]);
                vg[t] = fmaf(-wf[t], sum, pg[t]);
                c0 = fmaf(r0g[t], vg[t], c0);
            }
            c0 = bred1(c0, scrf, tid);
            if (fabsf(c0) < 1e-33f) break;
            alpha = __fdividef(rho, c0);

            // s = r - alpha*v ; publish
#pragma unroll
            for (int t = 0; t < RPT; t++) {
                sg[t] = fmaf(-alpha, vg[t], rg[t]);
                sf[tid + t * NT] = sg[t];
            }
            __syncthreads();

            // t = A_hat s ; st=<t,s>, tt=<t,t>
            float st = 0.0f, tt = 0.0f;
#pragma unroll
            for (int t = 0; t < RPT; t++) {
                const float sum = GATH(sf, pk[t][0], pk[t][1], pk[t][2]);
                tg[t] = fmaf(-wf[t], sum, sg[t]);
                st = fmaf(tg[t], sg[t], st);
                tt = fmaf(tg[t], tg[t], tt);
            }
            bred2(st, tt, scrf + 16, tid);
            if (!(tt > 0.0f)) {
#pragma unroll
                for (int t = 0; t < RPT; t++) dx[t] = fmaf(alpha, pg[t], dx[t]);
                break;
            }
            omega = __fdividef(st, tt);

            // dx += alpha p + omega s ; r = s - omega t ; EXACT new dots
            float r0r = 0.0f, rr = 0.0f;
#pragma unroll
            for (int t = 0; t < RPT; t++) {
                dx[t] = fmaf(alpha, pg[t], fmaf(omega, sg[t], dx[t]));
                rg[t] = fmaf(-omega, tg[t], sg[t]);
                r0r = fmaf(r0g[t], rg[t], r0r);
                rr  = fmaf(rg[t],  rg[t], rr);
            }
            bred2(r0r, rr, scrf + 48, tid);
            rho_o = rho; rho = r0r; rn2 = rr;
            if (rn2 <= tol2) break;
            if (rn2 < best) { best = rn2; since = 0; }
            else if (++since >= 6) break;
            if (fabsf(rho) < 1e-33f) break;
        }

        // ---- fold dx into fp64 x, compute true fp64 residual, restart ----
#pragma unroll
        for (int t = 0; t < RPT; t++) {
            const int i = tid + t * NT;
            xd[i] += (double)dx[t];
            dx[t] = 0.0f;
        }
        __syncthreads();
        double rp = 0.0;
#pragma unroll
        for (int t = 0; t < RPT; t++) {
            const int i = tid + t * NT;
            const uint32_t q0 = pk[t][0], q1 = pk[t][1], q2 = pk[t][2];
            double sum = *(const double*)((const char*)xd + ((q0 & 0xFFFFu) << 1))
                       + *(const double*)((const char*)xd + ((q0 >> 16)     << 1))
                       + *(const double*)((const char*)xd + ((q1 & 0xFFFFu) << 1))
                       + *(const double*)((const char*)xd + ((q1 >> 16)     << 1))
                       + *(const double*)((const char*)xd + ((q2 & 0xFFFFu) << 1))
                       + *(const double*)((const char*)xd + ((q2 >> 16)     << 1));
            double drec = 0.0, drho = 0.0;
#pragma unroll
            for (int c = 0; c < NCELL; c++) {
                double f = (double)cd[i * NCELL + c];
                drec += f * recK[c];
                drho += f * rho_p[c];
            }
            const double diag = 6.0 * Dp + AREA * (lam + drec);
            const double wdv  = Dp / diag;
            const double bh   = AREA * drho * B_SCALE / (A_SCALE * diag);
            const double rdi  = bh - (xd[i] - wdv * sum);
            const float  rdf  = (float)rdi;
            r0g[t] = rdf; rg[t] = rdf;
            pg[t] = 0.0f; vg[t] = 0.0f;
            rp += rdi * rdi;
        }
        rn2d = blk_red_d(rp, scrd, tid);   // also orders xd/r state for next pass
    }

    // ---- epilogue (fp64, one time) ----
    double part[NCELL] = {0, 0, 0, 0, 0};
#pragma unroll
    for (int t = 0; t < RPT; t++) {
        const int i = tid + t * NT;
        double num[NCELL], den = 0.0;
#pragma unroll
        for (int c = 0; c < NCELL; c++) {
            num[c] = (double)cd[i * NCELL + c] * rho_p[c];
            den += num[c];
        }
        const double gi = xd[i] / den;
#pragma unroll
        for (int c = 0; c < NCELL; c++) part[c] += gi * num[c];
    }
    double sc[NCELL];
#pragma unroll
    for (int c = 0; c < NCELL; c++) sc[c] = blk_red_d(part[c], scrd, tid);

    if (tid < 25) {
        const int a = tid / 5, c = tid % 5;
        g_IM[sys * 25 + tid] = K * rec[a] * sc[c] / (double)NROW;
        __threadfence();            // writer-side: make g_IM globally visible
    }
    __syncthreads();

    // ---- last block computes the loss ----
    if (tid == 0) {
        __threadfence();
        s_last = (atomicAdd(&g_cnt, 1) == 2) ? 1 : 0;
    }
    __syncthreads();
    if (s_last && tid < 32) {
        __threadfence();
        double s_m = 0, s_d = 0, s_mm = 0, s_dd = 0, s_md = 0;
        for (int i = tid; i < 75; i += 32) {
            const double m = *((volatile double*)&g_IM[i]);
            const double d = (double)Iexp[i];
            s_m += m; s_d += d; s_mm += m * m; s_dd += d * d; s_md += m * d;
        }
        s_m  = warp_red_d(s_m);
        s_d  = warp_red_d(s_d);
        s_mm = warp_red_d(s_mm);
        s_dd = warp_red_d(s_dd);
        s_md = warp_red_d(s_md);
        if (tid == 0) {
            const double n  = 75.0;
            const double mm = s_m / n, md = s_d / n;
            const double cov = s_md / n - mm * md;
            const double vm  = s_mm / n - mm * mm;
            const double vd  = s_dd / n - md * md;
            out[0] = (float)(1.0 - cov / (sqrt(vm) * sqrt(vd)));
            atomicExch(&g_cnt, 0);   // reset for next graph replay
        }
    }
}

extern "C" void kernel_launch(void* const* d_in, const int* in_sizes, int n_in,
                              void* d_out, int out_size)
{
    const float* th1  = (const float*)d_in[0];
    const float* th2  = (const float*)d_in[1];
    const float* th3  = (const float*)d_in[2];
    const float* cd   = (const float*)d_in[3];
    const float* Iexp = (const float*)d_in[4];
    const int*   nbr  = (const int*)d_in[5];

    cudaFuncSetAttribute(solve_kernel,
                         cudaFuncAttributeMaxDynamicSharedMemorySize, SM_BYTES);

    solve_kernel<<<3, NT, SM_BYTES>>>(th1, th2, th3, cd, Iexp, nbr, (float*)d_out);
}